// round 14
// baseline (speedup 1.0000x reference)
#include <cuda_runtime.h>
#include <cuda_fp16.h>
#include <math.h>
#include <stdint.h>

#define B_SZ   32768
#define NW     30
#define VOCAB  32000
#define WD     300
#define CH     400
#define AD     200

#define KQ_PAN 19      // ceil(300/16)
#define KF_PAN 57      // ceil(900/16)
#define NQ_PAD 640     // Q-gemm B rows padded (600 -> 640), multiple of 80

// ---------------- scratch (static device globals; no allocation) ----------------
__device__ __align__(16) float g_Mpi[KQ_PAN * 8 * 2 * NQ_PAD];   // pair-interleaved B (Q gemm)
__device__ __align__(16) float g_cvb[AD];
__device__ __align__(16) __half g_Qh[VOCAB * 600];               // fp16 Q table (38.4 MB)
__device__ __align__(16) float g_aT[NW * B_SZ];
__device__ float g_mx[NW];
__device__ float g_isum[NW];
__device__ float g_pm[NW * 8];
__device__ float g_ps[NW * 8];
__device__ __align__(16) float g_G[(size_t)B_SZ * 900];          // tf32-rounded [b][k*300+i]
__device__ float g_salpha[B_SZ];
__device__ __align__(16) float g_Wpi[KF_PAN * 8 * 2 * CH];       // pair-interleaved B (final)
__device__ __align__(16) float g_embT[VOCAB * WD];               // tf32-rounded emb copy
__device__ __align__(16) __half g_embH[VOCAB * WD];              // fp16 emb copy (19.2 MB)

__device__ __forceinline__ uint32_t f2tf32(float x)
{
    uint32_t r;
    asm("cvt.rna.tf32.f32 %0, %1;" : "=r"(r) : "f"(x));
    return r;
}
__device__ __forceinline__ float rtf32(float x) { return __uint_as_float(f2tf32(x)); }

// HW tanh: single MUFU op (sm_75+)
__device__ __forceinline__ float htanh(float x)
{
    float r;
    asm("tanh.approx.f32 %0, %1;" : "=f"(r) : "f"(x));
    return r;
}

// ---------------- prep kernels ----------------
// pair-interleaved B for Q gemm
__global__ void prep_Mpi_kernel(const float* __restrict__ conv_w, const float* __restrict__ v)
{
    int idx = blockIdx.x * blockDim.x + threadIdx.x;
    if (idx >= KQ_PAN * 8 * 2 * NQ_PAD) return;
    const int pan = idx / (8 * 2 * NQ_PAD);
    const int rem = idx % (8 * 2 * NQ_PAD);
    const int p   = rem / (2 * NQ_PAD);
    const int c   = rem % (2 * NQ_PAD);
    const int n   = c >> 1;
    const int j   = c & 1;
    const int k   = pan * 16 + ((p >> 2) << 3) + (p & 3) + j * 4;
    float val = 0.f;
    if (k < WD && n < 600) {
        const int ks = n / 200;
        const int a  = n % 200;
        float s = 0.f;
        #pragma unroll 4
        for (int o = 0; o < CH; o++)
            s += conv_w[o * (WD * 3) + k * 3 + ks] * v[o * AD + a];
        val = rtf32(s);
    }
    g_Mpi[idx] = val;
}

// pair-interleaved B for final gemm
__global__ void prep_Wpi_kernel(const float* __restrict__ conv_w)
{
    int idx = blockIdx.x * blockDim.x + threadIdx.x;
    if (idx >= KF_PAN * 8 * 2 * CH) return;
    const int pan = idx / (8 * 2 * CH);
    const int rem = idx % (8 * 2 * CH);
    const int p   = rem / (2 * CH);
    const int c   = rem % (2 * CH);
    const int n   = c >> 1;
    const int j   = c & 1;
    const int k   = pan * 16 + ((p >> 2) << 3) + (p & 3) + j * 4;
    float val = 0.f;
    if (k < 900) {
        const int sl = k / WD;
        const int i  = k % WD;
        val = rtf32(conv_w[n * 900 + i * 3 + sl]);
    }
    g_Wpi[idx] = val;
}

__global__ void prep_cvb_kernel(const float* __restrict__ conv_b,
                                const float* __restrict__ v,
                                const float* __restrict__ vb)
{
    int a = blockIdx.x * blockDim.x + threadIdx.x;
    if (a >= AD) return;
    float s = vb[a];
    for (int o = 0; o < CH; o++) s += conv_b[o] * v[o * AD + a];
    g_cvb[a] = s;
}

// one pass: emb -> tf32-rounded fp32 copy (Q-GEMM A) + fp16 copy (gbuild gathers)
__global__ void round_emb_kernel(const float* __restrict__ emb)
{
    int idx = blockIdx.x * blockDim.x + threadIdx.x;
    const int n4 = VOCAB * WD / 4;
    if (idx >= n4) return;
    float4 v = reinterpret_cast<const float4*>(emb)[idx];
    float4 t;
    t.x = rtf32(v.x); t.y = rtf32(v.y); t.z = rtf32(v.z); t.w = rtf32(v.w);
    reinterpret_cast<float4*>(g_embT)[idx] = t;
    uint2 h;
    *reinterpret_cast<__half2*>(&h.x) = __floats2half2_rn(v.x, v.y);
    *reinterpret_cast<__half2*>(&h.y) = __floats2half2_rn(v.z, v.w);
    reinterpret_cast<uint2*>(g_embH)[idx] = h;
}

// ---------------- tf32 mma.sync GEMM, pair-interleaved B, cp.async 4-stage -----
__device__ __forceinline__ void mma_tf32(float* c,
                                         uint32_t a0, uint32_t a1, uint32_t a2, uint32_t a3,
                                         uint32_t b0, uint32_t b1)
{
    asm volatile(
        "mma.sync.aligned.m16n8k8.row.col.f32.tf32.tf32.f32 "
        "{%0,%1,%2,%3}, {%4,%5,%6,%7}, {%8,%9}, {%0,%1,%2,%3};\n"
        : "+f"(c[0]), "+f"(c[1]), "+f"(c[2]), "+f"(c[3])
        : "r"(a0), "r"(a1), "r"(a2), "r"(a3), "r"(b0), "r"(b1));
}

__device__ __forceinline__ void cp16z(uint32_t dst, const void* src, int bytes)
{
    asm volatile("cp.async.cg.shared.global [%0], [%1], 16, %2;\n"
                 :: "r"(dst), "l"(src), "r"(bytes));
}
__device__ __forceinline__ void cp16(uint32_t dst, const void* src)
{
    asm volatile("cp.async.cg.shared.global [%0], [%1], 16;\n"
                 :: "r"(dst), "l"(src));
}

#define STAGES 4
#define AS_W 20                 // 16 k + 4 pad

template<int BN, int HOUT>
__global__ __launch_bounds__(128, 3)
void tgemm_kernel(const float* __restrict__ A, const float* __restrict__ Bpi,
                  void* __restrict__ Cv, int M, int N, int K, int NP,
                  const float* __restrict__ rs, const float* __restrict__ bias)
{
    constexpr int BP_W  = 2 * BN + 8;
    constexpr int BCH   = 8 * (2 * BN) / 4;
    constexpr int BRND  = (BCH + 127) / 128;
    constexpr int NT    = BN / 16;

    extern __shared__ __align__(16) uint32_t smem[];
    uint32_t* Asm = smem;
    uint32_t* Bsm = smem + STAGES * 128 * AS_W;
    const uint32_t as_base = (uint32_t)__cvta_generic_to_shared(Asm);
    const uint32_t bs_base = (uint32_t)__cvta_generic_to_shared(Bsm);

    const int tid    = threadIdx.x;
    const int lane   = tid & 31;
    const int warp   = tid >> 5;
    const int warp_m = warp & 1;
    const int warp_n = warp >> 1;
    const int m0 = blockIdx.y * 128;
    const int n0 = blockIdx.x * BN;

    const int am = tid >> 2;
    const int ak = (tid & 3) * 4;
    const int nIter = (K + 15) / 16;

    float acc[4][NT][4];
    #pragma unroll
    for (int mt = 0; mt < 4; mt++)
        #pragma unroll
        for (int nt = 0; nt < NT; nt++)
            #pragma unroll
            for (int i = 0; i < 4; i++) acc[mt][nt][i] = 0.f;

    auto issue_panel = [&](int pnl) {
        const int s   = pnl & (STAGES - 1);
        const int kk0 = pnl * 16;
        #pragma unroll
        for (int r = 0; r < 4; r++) {
            const int m  = am + r * 32;
            const int kg = kk0 + ak;
            int bytes = (K - kg) * 4;
            bytes = bytes < 0 ? 0 : (bytes > 16 ? 16 : bytes);
            const float* src = A + (size_t)(m0 + m) * K + (kg < K ? kg : 0);
            cp16z(as_base + (((s * 128 + m) * AS_W) + ak) * 4, src, bytes);
        }
        const float* bsrc0 = Bpi + ((size_t)pnl * 8) * (2 * NP) + 2 * n0;
        #pragma unroll
        for (int r = 0; r < BRND; r++) {
            const int idx = tid + r * 128;
            if (BCH % 128 == 0 || idx < BCH) {
                const int p  = idx / (2 * BN / 4);
                const int ch = idx % (2 * BN / 4);
                const float* src = bsrc0 + (size_t)p * (2 * NP) + ch * 4;
                cp16(bs_base + (((s * 8 + p) * BP_W) + ch * 4) * 4, src);
            }
        }
        asm volatile("cp.async.commit_group;\n");
    };

    issue_panel(0);
    issue_panel(1);
    issue_panel(2);

    for (int it = 0; it < nIter; ++it) {
        asm volatile("cp.async.wait_group %0;\n" :: "n"(STAGES - 2));
        __syncthreads();

        const int s = it & (STAGES - 1);
        const uint32_t* Asb = Asm + s * 128 * AS_W;
        const uint32_t* Bsb = Bsm + s * 8 * BP_W;

        #pragma unroll
        for (int ks = 0; ks < 2; ks++) {
            const int kb = ks * 8 + (lane & 3);
            const int pr = ks * 4 + (lane & 3);
            uint32_t af[4][4];
            uint32_t bf[NT][2];
            #pragma unroll
            for (int mt = 0; mt < 4; mt++) {
                const int rb = warp_m * 64 + mt * 16 + (lane >> 2);
                af[mt][0] = Asb[rb * AS_W + kb];
                af[mt][1] = Asb[(rb + 8) * AS_W + kb];
                af[mt][2] = Asb[rb * AS_W + kb + 4];
                af[mt][3] = Asb[(rb + 8) * AS_W + kb + 4];
            }
            #pragma unroll
            for (int nt = 0; nt < NT; nt++) {
                const int nc = warp_n * (BN / 2) + nt * 8 + (lane >> 2);
                uint2 bv = *reinterpret_cast<const uint2*>(&Bsb[pr * BP_W + nc * 2]);
                bf[nt][0] = bv.x;
                bf[nt][1] = bv.y;
            }
            #pragma unroll
            for (int mt = 0; mt < 4; mt++)
                #pragma unroll
                for (int nt = 0; nt < NT; nt++)
                    mma_tf32(acc[mt][nt], af[mt][0], af[mt][1], af[mt][2], af[mt][3],
                             bf[nt][0], bf[nt][1]);
        }

        if (it + STAGES - 1 < nIter) {
            issue_panel(it + STAGES - 1);
        } else {
            asm volatile("cp.async.commit_group;\n");
        }
    }

    // ---- epilogue ----
    #pragma unroll
    for (int mt = 0; mt < 4; mt++) {
        const int row0 = m0 + warp_m * 64 + mt * 16 + (lane >> 2);
        const int row1 = row0 + 8;
        const float r0 = rs ? rs[row0] : 0.f;
        const float r1 = rs ? rs[row1] : 0.f;
        #pragma unroll
        for (int nt = 0; nt < NT; nt++) {
            const int col = n0 + warp_n * (BN / 2) + nt * 8 + (lane & 3) * 2;
            if (col < N) {
                float v0 = acc[mt][nt][0], v1 = acc[mt][nt][1];
                float v2 = acc[mt][nt][2], v3 = acc[mt][nt][3];
                if (bias) {
                    const float b0 = bias[col], b1 = bias[col + 1];
                    v0 += r0 * b0; v1 += r0 * b1;
                    v2 += r1 * b0; v3 += r1 * b1;
                }
                if (HOUT) {
                    __half* Ch = (__half*)Cv;
                    *reinterpret_cast<__half2*>(Ch + (size_t)row0 * N + col) =
                        __floats2half2_rn(v0, v1);
                    *reinterpret_cast<__half2*>(Ch + (size_t)row1 * N + col) =
                        __floats2half2_rn(v2, v3);
                } else {
                    float* C = (float*)Cv;
                    *reinterpret_cast<float2*>(C + (size_t)row0 * N + col) = make_float2(v0, v1);
                    *reinterpret_cast<float2*>(C + (size_t)row1 * N + col) = make_float2(v2, v3);
                }
            }
        }
    }
}

#define SMEM3(BN) (STAGES * (128 * AS_W + 8 * (2 * (BN) + 8)) * 4)

// ---------------- scores: fp16 Q gathers + HW tanh ----------------
__global__ __launch_bounds__(256)
void score_kernel(const int* __restrict__ tok, const float* __restrict__ qv)
{
    __shared__ float4 sq[AD / 4];
    __shared__ float4 scvb[AD / 4];
    __shared__ int stok[8][NW];

    const int tid = threadIdx.x;
    const int wid = tid >> 5;
    const int lane = tid & 31;
    const int b = blockIdx.x * 8 + wid;

    if (tid < AD / 4) {
        sq[tid]   = reinterpret_cast<const float4*>(qv)[tid];
        scvb[tid] = reinterpret_cast<const float4*>(g_cvb)[tid];
    }
    if (lane < NW) stok[wid][lane] = tok[b * NW + lane];
    __syncthreads();

    for (int n = 0; n < NW; n++) {
        const int tc  = stok[wid][n];
        const int tp  = (n > 0)      ? stok[wid][n - 1] : -1;
        const int tn2 = (n < NW - 1) ? stok[wid][n + 1] : -1;
        const uint2* q1 = reinterpret_cast<const uint2*>(g_Qh + (size_t)tc * 600 + 200);
        const uint2* q0 = (tp  >= 0) ? reinterpret_cast<const uint2*>(g_Qh + (size_t)tp  * 600)       : nullptr;
        const uint2* q2 = (tn2 >= 0) ? reinterpret_cast<const uint2*>(g_Qh + (size_t)tn2 * 600 + 400) : nullptr;

        float s = 0.f;
        #pragma unroll
        for (int a4 = lane; a4 < AD / 4; a4 += 32) {
            float4 h = scvb[a4];
            {
                uint2 u = q1[a4];
                float2 lo = __half22float2(*reinterpret_cast<__half2*>(&u.x));
                float2 hi = __half22float2(*reinterpret_cast<__half2*>(&u.y));
                h.x += lo.x; h.y += lo.y; h.z += hi.x; h.w += hi.y;
            }
            if (q0) {
                uint2 u = q0[a4];
                float2 lo = __half22float2(*reinterpret_cast<__half2*>(&u.x));
                float2 hi = __half22float2(*reinterpret_cast<__half2*>(&u.y));
                h.x += lo.x; h.y += lo.y; h.z += hi.x; h.w += hi.y;
            }
            if (q2) {
                uint2 u = q2[a4];
                float2 lo = __half22float2(*reinterpret_cast<__half2*>(&u.x));
                float2 hi = __half22float2(*reinterpret_cast<__half2*>(&u.y));
                h.x += lo.x; h.y += lo.y; h.z += hi.x; h.w += hi.y;
            }
            float4 qq = sq[a4];
            s += htanh(h.x) * qq.x + htanh(h.y) * qq.y + htanh(h.z) * qq.z + htanh(h.w) * qq.w;
        }
        #pragma unroll
        for (int off = 16; off; off >>= 1)
            s += __shfl_down_sync(0xffffffffu, s, off);
        if (lane == 0) g_aT[n * B_SZ + b] = s;
    }
}

// ---------------- two-stage softmax stats over batch axis ----------------
__global__ __launch_bounds__(512)
void softmax_part_kernel()
{
    __shared__ float red[512];
    const int n = blockIdx.x;
    const int c = blockIdx.y;
    const int tid = threadIdx.x;
    const float* row = g_aT + (size_t)n * B_SZ + c * 4096;

    float mx = -INFINITY;
    #pragma unroll
    for (int i = 0; i < 8; i++) mx = fmaxf(mx, row[tid + i * 512]);
    red[tid] = mx;
    __syncthreads();
    for (int s = 256; s > 0; s >>= 1) {
        if (tid < s) red[tid] = fmaxf(red[tid], red[tid + s]);
        __syncthreads();
    }
    mx = red[0];
    __syncthreads();

    float sum = 0.f;
    #pragma unroll
    for (int i = 0; i < 8; i++) sum += __expf(row[tid + i * 512] - mx);
    red[tid] = sum;
    __syncthreads();
    for (int s = 256; s > 0; s >>= 1) {
        if (tid < s) red[tid] += red[tid + s];
        __syncthreads();
    }
    if (tid == 0) { g_pm[n * 8 + c] = mx; g_ps[n * 8 + c] = red[0]; }
}

__global__ void softmax_comb_kernel()
{
    const int n = threadIdx.x;
    if (n >= NW) return;
    float M = -INFINITY;
    #pragma unroll
    for (int c = 0; c < 8; c++) M = fmaxf(M, g_pm[n * 8 + c]);
    float S = 0.f;
    #pragma unroll
    for (int c = 0; c < 8; c++) S += g_ps[n * 8 + c] * __expf(g_pm[n * 8 + c] - M);
    g_mx[n] = M;
    g_isum[n] = 1.f / S;
}

// ---------------- build G (fp16 emb gathers, tf32-rounded fp32 output) ----------
__global__ __launch_bounds__(96)
void gbuild_kernel(const int* __restrict__ tok)
{
    __shared__ float sal[NW + 2];
    __shared__ int stok[NW];
    const int b = blockIdx.x;
    const int tid = threadIdx.x;

    if (tid < NW) {
        sal[tid + 1] = __expf(g_aT[tid * B_SZ + b] - g_mx[tid]) * g_isum[tid];
        stok[tid] = tok[b * NW + tid];
    }
    if (tid == NW)     sal[0] = 0.f;
    if (tid == NW + 1) sal[NW + 1] = 0.f;
    __syncthreads();

    if (tid == 0) {
        float s = 0.f;
        #pragma unroll
        for (int n = 1; n <= NW; n++) s += sal[n];
        g_salpha[b] = s;
    }

    if (tid < WD / 4) {
        float4 g0 = make_float4(0.f, 0.f, 0.f, 0.f);
        float4 g1 = g0, g2 = g0;
        #pragma unroll
        for (int m = 0; m < NW; m++) {
            const uint2 u = reinterpret_cast<const uint2*>(
                g_embH + (size_t)stok[m] * WD)[tid];
            const float2 lo = __half22float2(*reinterpret_cast<const __half2*>(&u.x));
            const float2 hi = __half22float2(*reinterpret_cast<const __half2*>(&u.y));
            const float w1 = sal[m + 1];
            const float w0 = sal[m + 2];
            const float w2 = sal[m];
            g1.x += w1 * lo.x; g1.y += w1 * lo.y; g1.z += w1 * hi.x; g1.w += w1 * hi.y;
            g0.x += w0 * lo.x; g0.y += w0 * lo.y; g0.z += w0 * hi.x; g0.w += w0 * hi.y;
            g2.x += w2 * lo.x; g2.y += w2 * lo.y; g2.z += w2 * hi.x; g2.w += w2 * hi.y;
        }
        g0.x = rtf32(g0.x); g0.y = rtf32(g0.y); g0.z = rtf32(g0.z); g0.w = rtf32(g0.w);
        g1.x = rtf32(g1.x); g1.y = rtf32(g1.y); g1.z = rtf32(g1.z); g1.w = rtf32(g1.w);
        g2.x = rtf32(g2.x); g2.y = rtf32(g2.y); g2.z = rtf32(g2.z); g2.w = rtf32(g2.w);
        float4* gp = reinterpret_cast<float4*>(g_G + (size_t)b * 900);
        gp[tid]            = g0;
        gp[WD / 4 + tid]   = g1;
        gp[WD / 2 + tid]   = g2;
    }
}

// ---------------- launch ----------------
extern "C" void kernel_launch(void* const* d_in, const int* in_sizes, int n_in,
                              void* d_out, int out_size)
{
    const int*   tok    = (const int*)  d_in[0];
    const float* emb    = (const float*)d_in[1];
    const float* conv_w = (const float*)d_in[2];
    const float* conv_b = (const float*)d_in[3];
    const float* v      = (const float*)d_in[4];
    const float* vb     = (const float*)d_in[5];
    const float* q      = (const float*)d_in[6];
    float* out = (float*)d_out;

    float *pMpi, *pG, *pWpi, *psal, *pembT;
    __half* pQh;
    cudaGetSymbolAddress((void**)&pMpi,  g_Mpi);
    cudaGetSymbolAddress((void**)&pQh,   g_Qh);
    cudaGetSymbolAddress((void**)&pG,    g_G);
    cudaGetSymbolAddress((void**)&pWpi,  g_Wpi);
    cudaGetSymbolAddress((void**)&psal,  g_salpha);
    cudaGetSymbolAddress((void**)&pembT, g_embT);

    cudaFuncSetAttribute((const void*)tgemm_kernel<80, 0>,
                         cudaFuncAttributeMaxDynamicSharedMemorySize, SMEM3(80));
    cudaFuncSetAttribute((const void*)tgemm_kernel<80, 1>,
                         cudaFuncAttributeMaxDynamicSharedMemorySize, SMEM3(80));

    // 1. prep (pair-interleaved B operands) + emb copies (tf32 + fp16, one pass)
    prep_Mpi_kernel<<<(KQ_PAN * 8 * 2 * NQ_PAD + 255) / 256, 256>>>(conv_w, v);
    prep_cvb_kernel<<<1, 256>>>(conv_b, v, vb);
    prep_Wpi_kernel<<<(KF_PAN * 8 * 2 * CH + 255) / 256, 256>>>(conv_w);
    round_emb_kernel<<<(VOCAB * WD / 4 + 255) / 256, 256>>>(emb);

    // 2. Q = embT @ M : [32000,300] x [300,600] -> fp16 Q table
    {
        dim3 grid(NQ_PAD / 80, VOCAB / 128);
        tgemm_kernel<80, 1><<<grid, 128, SMEM3(80)>>>(pembT, pMpi, (void*)pQh,
                                                      VOCAB, 600, WD, NQ_PAD,
                                                      nullptr, nullptr);
    }

    // 3. attention scores (fp16 gathers, HW tanh)
    score_kernel<<<B_SZ / 8, 256>>>(tok, q);

    // 4. softmax stats (two-stage)
    {
        dim3 pgrid(NW, 8);
        softmax_part_kernel<<<pgrid, 512>>>();
        softmax_comb_kernel<<<1, 32>>>();
    }

    // 5. build G (fp16 emb gathers) and sum-alpha
    gbuild_kernel<<<B_SZ, 96>>>(tok);

    // 6. e = G @ Wc2 + salpha * conv_b : [32768,900] x [900,400]
    {
        dim3 grid(CH / 80, B_SZ / 128);
        tgemm_kernel<80, 0><<<grid, 128, SMEM3(80)>>>(pG, pWpi, (void*)out,
                                                      B_SZ, CH, 900, CH,
                                                      psal, conv_b);
    }
}

// round 16
// speedup vs baseline: 1.1273x; 1.1273x over previous
#include <cuda_runtime.h>
#include <cuda_fp16.h>
#include <math.h>
#include <stdint.h>

#define B_SZ   32768
#define NW     30
#define VOCAB  32000
#define WD     300
#define CH     400
#define AD     200

#define KQ_PAN 19      // ceil(300/16)
#define NQ_PAD 640     // Q-gemm B rows padded (600 -> 640), multiple of 80
#define KF_PAN 57      // ceil(900/16)
#define KF_PAD (KF_PAN * 16)    // 912

// ---------------- scratch (static device globals; no allocation) ----------------
__device__ __align__(16) float  g_Mpi[KQ_PAN * 8 * 2 * NQ_PAD];  // pair-interleaved tf32 B (Q gemm)
__device__ __align__(16) float  g_cvb[AD];
__device__ __align__(16) __half g_Qh[VOCAB * 600];               // fp16 Q table (38.4 MB)
__device__ __align__(16) float  g_aT[NW * B_SZ];
__device__ float g_mx[NW];
__device__ float g_isum[NW];
__device__ float g_pm[NW * 8];
__device__ float g_ps[NW * 8];
__device__ __align__(16) __half g_Gh[(size_t)B_SZ * KF_PAD];     // fp16 G, plain layout (59.8 MB)
__device__ float g_salpha[B_SZ];
__device__ __align__(16) __half g_Wh[KF_PAN * 4 * CH * 4];       // fp16 B-quad layout
__device__ __align__(16) float  g_embT[VOCAB * WD];              // tf32-rounded emb copy

__device__ __forceinline__ uint32_t f2tf32(float x)
{
    uint32_t r;
    asm("cvt.rna.tf32.f32 %0, %1;" : "=r"(r) : "f"(x));
    return r;
}
__device__ __forceinline__ float rtf32(float x) { return __uint_as_float(f2tf32(x)); }

// HW tanh: single MUFU op (sm_75+)
__device__ __forceinline__ float htanh(float x)
{
    float r;
    asm("tanh.approx.f32 %0, %1;" : "=f"(r) : "f"(x));
    return r;
}

// ---------------- prep kernels ----------------
// pair-interleaved tf32 B for Q gemm (layout proven R9-R14)
__global__ void prep_Mpi_kernel(const float* __restrict__ conv_w, const float* __restrict__ v)
{
    int idx = blockIdx.x * blockDim.x + threadIdx.x;
    if (idx >= KQ_PAN * 8 * 2 * NQ_PAD) return;
    const int pan = idx / (8 * 2 * NQ_PAD);
    const int rem = idx % (8 * 2 * NQ_PAD);
    const int p   = rem / (2 * NQ_PAD);
    const int c   = rem % (2 * NQ_PAD);
    const int n   = c >> 1;
    const int j   = c & 1;
    const int k   = pan * 16 + ((p >> 2) << 3) + (p & 3) + j * 4;
    float val = 0.f;
    if (k < WD && n < 600) {
        const int ks = n / 200;
        const int a  = n % 200;
        float s = 0.f;
        #pragma unroll 4
        for (int o = 0; o < CH; o++)
            s += conv_w[o * (WD * 3) + k * 3 + ks] * v[o * AD + a];
        val = rtf32(s);
    }
    g_Mpi[idx] = val;
}

// fp16 B-quad layout for final gemm (validated correct in R12):
// g_Wh[((pnl*4 + j)*CH + n)*4 + q] = Wc2[k][n], k = pnl*16 + 2j + (q&1) + (q>>1)*8
__global__ void prep_Wh_kernel(const float* __restrict__ conv_w)
{
    int idx = blockIdx.x * blockDim.x + threadIdx.x;
    if (idx >= KF_PAN * 4 * CH * 4) return;
    const int q   = idx & 3;
    const int n   = (idx >> 2) % CH;
    const int j   = ((idx >> 2) / CH) & 3;
    const int pnl = idx / (4 * CH * 4);
    const int k   = pnl * 16 + 2 * j + (q & 1) + (q >> 1) * 8;
    float val = 0.f;
    if (k < 900) {
        const int sl = k / WD;
        const int i  = k % WD;
        val = conv_w[n * 900 + i * 3 + sl];
    }
    g_Wh[idx] = __float2half_rn(val);
}

__global__ void prep_cvb_kernel(const float* __restrict__ conv_b,
                                const float* __restrict__ v,
                                const float* __restrict__ vb)
{
    int a = blockIdx.x * blockDim.x + threadIdx.x;
    if (a >= AD) return;
    float s = vb[a];
    for (int o = 0; o < CH; o++) s += conv_b[o] * v[o * AD + a];
    g_cvb[a] = s;
}

__global__ void round_emb_kernel(const float* __restrict__ emb)
{
    int idx = blockIdx.x * blockDim.x + threadIdx.x;
    const int n4 = VOCAB * WD / 4;
    if (idx >= n4) return;
    float4 v = reinterpret_cast<const float4*>(emb)[idx];
    v.x = rtf32(v.x); v.y = rtf32(v.y); v.z = rtf32(v.z); v.w = rtf32(v.w);
    reinterpret_cast<float4*>(g_embT)[idx] = v;
}

// ---------------- common asm helpers ----------------
__device__ __forceinline__ void mma_tf32(float* c,
                                         uint32_t a0, uint32_t a1, uint32_t a2, uint32_t a3,
                                         uint32_t b0, uint32_t b1)
{
    asm volatile(
        "mma.sync.aligned.m16n8k8.row.col.f32.tf32.tf32.f32 "
        "{%0,%1,%2,%3}, {%4,%5,%6,%7}, {%8,%9}, {%0,%1,%2,%3};\n"
        : "+f"(c[0]), "+f"(c[1]), "+f"(c[2]), "+f"(c[3])
        : "r"(a0), "r"(a1), "r"(a2), "r"(a3), "r"(b0), "r"(b1));
}
__device__ __forceinline__ void mma_f16(float* c,
                                        uint32_t a0, uint32_t a1, uint32_t a2, uint32_t a3,
                                        uint32_t b0, uint32_t b1)
{
    asm volatile(
        "mma.sync.aligned.m16n8k16.row.col.f32.f16.f16.f32 "
        "{%0,%1,%2,%3}, {%4,%5,%6,%7}, {%8,%9}, {%0,%1,%2,%3};\n"
        : "+f"(c[0]), "+f"(c[1]), "+f"(c[2]), "+f"(c[3])
        : "r"(a0), "r"(a1), "r"(a2), "r"(a3), "r"(b0), "r"(b1));
}
__device__ __forceinline__ void cp16z(uint32_t dst, const void* src, int bytes)
{
    asm volatile("cp.async.cg.shared.global [%0], [%1], 16, %2;\n"
                 :: "r"(dst), "l"(src), "r"(bytes));
}
__device__ __forceinline__ void cp16(uint32_t dst, const void* src)
{
    asm volatile("cp.async.cg.shared.global [%0], [%1], 16;\n"
                 :: "r"(dst), "l"(src));
}

#define STAGES 4
#define AS_W 20                 // 16 k + 4 pad (tf32 gemm)

// ---------------- tf32 mma.sync GEMM (Q gemm; R13-proven), fp16 output ----------
template<int BN>
__global__ __launch_bounds__(128, 3)
void tgemm_kernel(const float* __restrict__ A, const float* __restrict__ Bpi,
                  __half* __restrict__ C, int M, int N, int K, int NP)
{
    constexpr int BP_W  = 2 * BN + 8;
    constexpr int BCH   = 8 * (2 * BN) / 4;
    constexpr int BRND  = (BCH + 127) / 128;
    constexpr int NT    = BN / 16;

    extern __shared__ __align__(16) uint32_t smem[];
    uint32_t* Asm = smem;
    uint32_t* Bsm = smem + STAGES * 128 * AS_W;
    const uint32_t as_base = (uint32_t)__cvta_generic_to_shared(Asm);
    const uint32_t bs_base = (uint32_t)__cvta_generic_to_shared(Bsm);

    const int tid    = threadIdx.x;
    const int lane   = tid & 31;
    const int warp   = tid >> 5;
    const int warp_m = warp & 1;
    const int warp_n = warp >> 1;
    const int m0 = blockIdx.y * 128;
    const int n0 = blockIdx.x * BN;

    const int am = tid >> 2;
    const int ak = (tid & 3) * 4;
    const int nIter = (K + 15) / 16;

    float acc[4][NT][4];
    #pragma unroll
    for (int mt = 0; mt < 4; mt++)
        #pragma unroll
        for (int nt = 0; nt < NT; nt++)
            #pragma unroll
            for (int i = 0; i < 4; i++) acc[mt][nt][i] = 0.f;

    auto issue_panel = [&](int pnl) {
        const int s   = pnl & (STAGES - 1);
        const int kk0 = pnl * 16;
        #pragma unroll
        for (int r = 0; r < 4; r++) {
            const int m  = am + r * 32;
            const int kg = kk0 + ak;
            int bytes = (K - kg) * 4;
            bytes = bytes < 0 ? 0 : (bytes > 16 ? 16 : bytes);
            const float* src = A + (size_t)(m0 + m) * K + (kg < K ? kg : 0);
            cp16z(as_base + (((s * 128 + m) * AS_W) + ak) * 4, src, bytes);
        }
        const float* bsrc0 = Bpi + ((size_t)pnl * 8) * (2 * NP) + 2 * n0;
        #pragma unroll
        for (int r = 0; r < BRND; r++) {
            const int idx = tid + r * 128;
            if (BCH % 128 == 0 || idx < BCH) {
                const int p  = idx / (2 * BN / 4);
                const int ch = idx % (2 * BN / 4);
                const float* src = bsrc0 + (size_t)p * (2 * NP) + ch * 4;
                cp16(bs_base + (((s * 8 + p) * BP_W) + ch * 4) * 4, src);
            }
        }
        asm volatile("cp.async.commit_group;\n");
    };

    issue_panel(0);
    issue_panel(1);
    issue_panel(2);

    for (int it = 0; it < nIter; ++it) {
        asm volatile("cp.async.wait_group %0;\n" :: "n"(STAGES - 2));
        __syncthreads();

        const int s = it & (STAGES - 1);
        const uint32_t* Asb = Asm + s * 128 * AS_W;
        const uint32_t* Bsb = Bsm + s * 8 * BP_W;

        #pragma unroll
        for (int ks = 0; ks < 2; ks++) {
            const int kb = ks * 8 + (lane & 3);
            const int pr = ks * 4 + (lane & 3);
            uint32_t af[4][4];
            uint32_t bf[NT][2];
            #pragma unroll
            for (int mt = 0; mt < 4; mt++) {
                const int rb = warp_m * 64 + mt * 16 + (lane >> 2);
                af[mt][0] = Asb[rb * AS_W + kb];
                af[mt][1] = Asb[(rb + 8) * AS_W + kb];
                af[mt][2] = Asb[rb * AS_W + kb + 4];
                af[mt][3] = Asb[(rb + 8) * AS_W + kb + 4];
            }
            #pragma unroll
            for (int nt = 0; nt < NT; nt++) {
                const int nc = warp_n * (BN / 2) + nt * 8 + (lane >> 2);
                uint2 bv = *reinterpret_cast<const uint2*>(&Bsb[pr * BP_W + nc * 2]);
                bf[nt][0] = bv.x;
                bf[nt][1] = bv.y;
            }
            #pragma unroll
            for (int mt = 0; mt < 4; mt++)
                #pragma unroll
                for (int nt = 0; nt < NT; nt++)
                    mma_tf32(acc[mt][nt], af[mt][0], af[mt][1], af[mt][2], af[mt][3],
                             bf[nt][0], bf[nt][1]);
        }

        if (it + STAGES - 1 < nIter) {
            issue_panel(it + STAGES - 1);
        } else {
            asm volatile("cp.async.commit_group;\n");
        }
    }

    #pragma unroll
    for (int mt = 0; mt < 4; mt++) {
        const int row0 = m0 + warp_m * 64 + mt * 16 + (lane >> 2);
        const int row1 = row0 + 8;
        #pragma unroll
        for (int nt = 0; nt < NT; nt++) {
            const int col = n0 + warp_n * (BN / 2) + nt * 8 + (lane & 3) * 2;
            if (col < N) {
                *reinterpret_cast<__half2*>(C + (size_t)row0 * N + col) =
                    __floats2half2_rn(acc[mt][nt][0], acc[mt][nt][1]);
                *reinterpret_cast<__half2*>(C + (size_t)row1 * N + col) =
                    __floats2half2_rn(acc[mt][nt][2], acc[mt][nt][3]);
            }
        }
    }
}

#define SMEM3(BN) (STAGES * (128 * AS_W + 8 * (2 * (BN) + 8)) * 4)

// ---------------- fp16 HMMA GEMM (final gemm) ----------------
// C[32768,400] = Gh[32768,912] @ Wh + rs[m]*bias[n].
// Gh: plain row layout, 912 halfs/row (pad halfs zero). Wh: B-quad layout.
// Block 128x80, 128 threads, warp tile 64x40, NT=5, 57 k16 panels.
#define HA_W 12       // 8 data words + 4 pad (48B rows, 16B-aligned, conflict-free)
#define HB_W 168      // 160 data + 8 pad
#define HST_W (128 * HA_W + 4 * HB_W)    // 2208 words/stage
#define HSMEM (STAGES * HST_W * 4)       // 35328 bytes

__global__ __launch_bounds__(128, 3)
void hgemm_kernel(const __half* __restrict__ Gh, const __half* __restrict__ Wh,
                  float* __restrict__ C,
                  const float* __restrict__ rs, const float* __restrict__ bias)
{
    extern __shared__ __align__(16) uint32_t smem[];
    const uint32_t s_base = (uint32_t)__cvta_generic_to_shared(smem);

    const int tid    = threadIdx.x;
    const int lane   = tid & 31;
    const int warp   = tid >> 5;
    const int warp_m = warp & 1;
    const int warp_n = warp >> 1;
    const int m0 = blockIdx.y * 128;
    const int n0 = blockIdx.x * 80;

    float acc[4][5][4];
    #pragma unroll
    for (int mt = 0; mt < 4; mt++)
        #pragma unroll
        for (int nt = 0; nt < 5; nt++)
            #pragma unroll
            for (int i = 0; i < 4; i++) acc[mt][nt][i] = 0.f;

    auto issue_panel = [&](int pnl) {
        const int s = pnl & (STAGES - 1);
        const uint32_t abase = s_base + (s * HST_W) * 4;
        const uint32_t bbase = abase + 128 * HA_W * 4;
        // A: 128 rows x 2 x 16B chunks = 256 -> 2 per thread
        #pragma unroll
        for (int r = 0; r < 2; r++) {
            const int idx = tid + r * 128;
            const int row = idx >> 1;
            const int ch  = idx & 1;
            const __half* src = Gh + (size_t)(m0 + row) * KF_PAD + pnl * 16 + ch * 8;
            cp16(abase + (row * HA_W + ch * 4) * 4, src);
        }
        // B: 4 j-rows x 40 x 16B chunks = 160
        #pragma unroll
        for (int r = 0; r < 2; r++) {
            const int idx = tid + r * 128;
            if (idx < 160) {
                const int j  = idx / 40;
                const int ch = idx % 40;
                const __half* src = Wh + ((size_t)(pnl * 4 + j) * CH + n0) * 4 + ch * 8;
                cp16(bbase + (j * HB_W + ch * 4) * 4, src);
            }
        }
        asm volatile("cp.async.commit_group;\n");
    };

    issue_panel(0);
    issue_panel(1);
    issue_panel(2);

    for (int it = 0; it < KF_PAN; ++it) {
        asm volatile("cp.async.wait_group %0;\n" :: "n"(STAGES - 2));
        __syncthreads();

        const int s = it & (STAGES - 1);
        const uint32_t* Asb = smem + s * HST_W;
        const uint32_t* Bsb = Asb + 128 * HA_W;

        const int j = lane & 3;
        uint32_t af[4][4];
        uint32_t bf[5][2];
        #pragma unroll
        for (int mt = 0; mt < 4; mt++) {
            const int rb = warp_m * 64 + mt * 16 + (lane >> 2);
            af[mt][0] = Asb[rb * HA_W + j];            // row rb,   halfs 2j,2j+1
            af[mt][1] = Asb[(rb + 8) * HA_W + j];      // row rb+8
            af[mt][2] = Asb[rb * HA_W + j + 4];        // row rb,   halfs 2j+8,2j+9
            af[mt][3] = Asb[(rb + 8) * HA_W + j + 4];
        }
        #pragma unroll
        for (int nt = 0; nt < 5; nt++) {
            const int nc = warp_n * 40 + nt * 8 + (lane >> 2);
            uint2 bv = *reinterpret_cast<const uint2*>(&Bsb[j * HB_W + nc * 2]);
            bf[nt][0] = bv.x;
            bf[nt][1] = bv.y;
        }
        #pragma unroll
        for (int mt = 0; mt < 4; mt++)
            #pragma unroll
            for (int nt = 0; nt < 5; nt++)
                mma_f16(acc[mt][nt], af[mt][0], af[mt][1], af[mt][2], af[mt][3],
                        bf[nt][0], bf[nt][1]);

        if (it + STAGES - 1 < KF_PAN) {
            issue_panel(it + STAGES - 1);
        } else {
            asm volatile("cp.async.commit_group;\n");
        }
    }

    #pragma unroll
    for (int mt = 0; mt < 4; mt++) {
        const int row0 = m0 + warp_m * 64 + mt * 16 + (lane >> 2);
        const int row1 = row0 + 8;
        const float r0 = rs[row0];
        const float r1 = rs[row1];
        #pragma unroll
        for (int nt = 0; nt < 5; nt++) {
            const int col = n0 + warp_n * 40 + nt * 8 + (lane & 3) * 2;
            const float b0 = bias[col], b1 = bias[col + 1];
            *reinterpret_cast<float2*>(C + (size_t)row0 * CH + col) =
                make_float2(acc[mt][nt][0] + r0 * b0, acc[mt][nt][1] + r0 * b1);
            *reinterpret_cast<float2*>(C + (size_t)row1 * CH + col) =
                make_float2(acc[mt][nt][2] + r1 * b0, acc[mt][nt][3] + r1 * b1);
        }
    }
}

// ---------------- scores: fp16 Q gathers + HW tanh ----------------
__global__ __launch_bounds__(256)
void score_kernel(const int* __restrict__ tok, const float* __restrict__ qv)
{
    __shared__ float4 sq[AD / 4];
    __shared__ float4 scvb[AD / 4];
    __shared__ int stok[8][NW];

    const int tid = threadIdx.x;
    const int wid = tid >> 5;
    const int lane = tid & 31;
    const int b = blockIdx.x * 8 + wid;

    if (tid < AD / 4) {
        sq[tid]   = reinterpret_cast<const float4*>(qv)[tid];
        scvb[tid] = reinterpret_cast<const float4*>(g_cvb)[tid];
    }
    if (lane < NW) stok[wid][lane] = tok[b * NW + lane];
    __syncthreads();

    for (int n = 0; n < NW; n++) {
        const int tc  = stok[wid][n];
        const int tp  = (n > 0)      ? stok[wid][n - 1] : -1;
        const int tn2 = (n < NW - 1) ? stok[wid][n + 1] : -1;
        const uint2* q1 = reinterpret_cast<const uint2*>(g_Qh + (size_t)tc * 600 + 200);
        const uint2* q0 = (tp  >= 0) ? reinterpret_cast<const uint2*>(g_Qh + (size_t)tp  * 600)       : nullptr;
        const uint2* q2 = (tn2 >= 0) ? reinterpret_cast<const uint2*>(g_Qh + (size_t)tn2 * 600 + 400) : nullptr;

        float s = 0.f;
        #pragma unroll
        for (int a4 = lane; a4 < AD / 4; a4 += 32) {
            float4 h = scvb[a4];
            {
                uint2 u = q1[a4];
                float2 lo = __half22float2(*reinterpret_cast<__half2*>(&u.x));
                float2 hi = __half22float2(*reinterpret_cast<__half2*>(&u.y));
                h.x += lo.x; h.y += lo.y; h.z += hi.x; h.w += hi.y;
            }
            if (q0) {
                uint2 u = q0[a4];
                float2 lo = __half22float2(*reinterpret_cast<__half2*>(&u.x));
                float2 hi = __half22float2(*reinterpret_cast<__half2*>(&u.y));
                h.x += lo.x; h.y += lo.y; h.z += hi.x; h.w += hi.y;
            }
            if (q2) {
                uint2 u = q2[a4];
                float2 lo = __half22float2(*reinterpret_cast<__half2*>(&u.x));
                float2 hi = __half22float2(*reinterpret_cast<__half2*>(&u.y));
                h.x += lo.x; h.y += lo.y; h.z += hi.x; h.w += hi.y;
            }
            float4 qq = sq[a4];
            s += htanh(h.x) * qq.x + htanh(h.y) * qq.y + htanh(h.z) * qq.z + htanh(h.w) * qq.w;
        }
        #pragma unroll
        for (int off = 16; off; off >>= 1)
            s += __shfl_down_sync(0xffffffffu, s, off);
        if (lane == 0) g_aT[n * B_SZ + b] = s;
    }
}

// ---------------- two-stage softmax stats ----------------
__global__ __launch_bounds__(512)
void softmax_part_kernel()
{
    __shared__ float red[512];
    const int n = blockIdx.x;
    const int c = blockIdx.y;
    const int tid = threadIdx.x;
    const float* row = g_aT + (size_t)n * B_SZ + c * 4096;

    float mx = -INFINITY;
    #pragma unroll
    for (int i = 0; i < 8; i++) mx = fmaxf(mx, row[tid + i * 512]);
    red[tid] = mx;
    __syncthreads();
    for (int s = 256; s > 0; s >>= 1) {
        if (tid < s) red[tid] = fmaxf(red[tid], red[tid + s]);
        __syncthreads();
    }
    mx = red[0];
    __syncthreads();

    float sum = 0.f;
    #pragma unroll
    for (int i = 0; i < 8; i++) sum += __expf(row[tid + i * 512] - mx);
    red[tid] = sum;
    __syncthreads();
    for (int s = 256; s > 0; s >>= 1) {
        if (tid < s) red[tid] += red[tid + s];
        __syncthreads();
    }
    if (tid == 0) { g_pm[n * 8 + c] = mx; g_ps[n * 8 + c] = red[0]; }
}

__global__ void softmax_comb_kernel()
{
    const int n = threadIdx.x;
    if (n >= NW) return;
    float M = -INFINITY;
    #pragma unroll
    for (int c = 0; c < 8; c++) M = fmaxf(M, g_pm[n * 8 + c]);
    float S = 0.f;
    #pragma unroll
    for (int c = 0; c < 8; c++) S += g_ps[n * 8 + c] * __expf(g_pm[n * 8 + c] - M);
    g_mx[n] = M;
    g_isum[n] = 1.f / S;
}

// ---------------- build G (fp32 emb gathers, fp16 coalesced plain stores) -------
__global__ __launch_bounds__(96)
void gbuild_kernel(const int* __restrict__ tok, const float* __restrict__ emb)
{
    __shared__ float sal[NW + 2];
    __shared__ int stok[NW];
    const int b = blockIdx.x;
    const int tid = threadIdx.x;

    if (tid < NW) {
        sal[tid + 1] = __expf(g_aT[tid * B_SZ + b] - g_mx[tid]) * g_isum[tid];
        stok[tid] = tok[b * NW + tid];
    }
    if (tid == NW)     sal[0] = 0.f;
    if (tid == NW + 1) sal[NW + 1] = 0.f;
    __syncthreads();

    if (tid == 0) {
        float s = 0.f;
        #pragma unroll
        for (int n = 1; n <= NW; n++) s += sal[n];
        g_salpha[b] = s;
    }

    if (tid < WD / 4) {
        float4 g0 = make_float4(0.f, 0.f, 0.f, 0.f);
        float4 g1 = g0, g2 = g0;
        #pragma unroll
        for (int m = 0; m < NW; m++) {
            const float4 e = reinterpret_cast<const float4*>(
                emb + (size_t)stok[m] * WD)[tid];
            const float w1 = sal[m + 1];
            const float w0 = sal[m + 2];
            const float w2 = sal[m];
            g1.x += w1 * e.x; g1.y += w1 * e.y; g1.z += w1 * e.z; g1.w += w1 * e.w;
            g0.x += w0 * e.x; g0.y += w0 * e.y; g0.z += w0 * e.z; g0.w += w0 * e.w;
            g2.x += w2 * e.x; g2.y += w2 * e.y; g2.z += w2 * e.z; g2.w += w2 * e.w;
        }
        // fp16 plain-layout stores: slice sl at half-offset sl*300 + tid*4 (8B aligned)
        __half* gp = g_Gh + (size_t)b * KF_PAD;
        uint2 u0, u1, u2;
        *reinterpret_cast<__half2*>(&u0.x) = __floats2half2_rn(g0.x, g0.y);
        *reinterpret_cast<__half2*>(&u0.y) = __floats2half2_rn(g0.z, g0.w);
        *reinterpret_cast<__half2*>(&u1.x) = __floats2half2_rn(g1.x, g1.y);
        *reinterpret_cast<__half2*>(&u1.y) = __floats2half2_rn(g1.z, g1.w);
        *reinterpret_cast<__half2*>(&u2.x) = __floats2half2_rn(g2.x, g2.y);
        *reinterpret_cast<__half2*>(&u2.y) = __floats2half2_rn(g2.z, g2.w);
        *reinterpret_cast<uint2*>(gp +           tid * 4) = u0;
        *reinterpret_cast<uint2*>(gp + 300 +     tid * 4) = u1;
        *reinterpret_cast<uint2*>(gp + 600 +     tid * 4) = u2;
    }
}

// ---------------- launch ----------------
extern "C" void kernel_launch(void* const* d_in, const int* in_sizes, int n_in,
                              void* d_out, int out_size)
{
    const int*   tok    = (const int*)  d_in[0];
    const float* emb    = (const float*)d_in[1];
    const float* conv_w = (const float*)d_in[2];
    const float* conv_b = (const float*)d_in[3];
    const float* v      = (const float*)d_in[4];
    const float* vb     = (const float*)d_in[5];
    const float* q      = (const float*)d_in[6];
    float* out = (float*)d_out;

    float *pMpi, *psal, *pembT;
    __half *pQh, *pGh, *pWh;
    cudaGetSymbolAddress((void**)&pMpi,  g_Mpi);
    cudaGetSymbolAddress((void**)&pQh,   g_Qh);
    cudaGetSymbolAddress((void**)&pGh,   g_Gh);
    cudaGetSymbolAddress((void**)&pWh,   g_Wh);
    cudaGetSymbolAddress((void**)&psal,  g_salpha);
    cudaGetSymbolAddress((void**)&pembT, g_embT);

    cudaFuncSetAttribute((const void*)tgemm_kernel<80>,
                         cudaFuncAttributeMaxDynamicSharedMemorySize, SMEM3(80));
    cudaFuncSetAttribute((const void*)hgemm_kernel,
                         cudaFuncAttributeMaxDynamicSharedMemorySize, HSMEM);

    // 1. prep
    prep_Mpi_kernel<<<(KQ_PAN * 8 * 2 * NQ_PAD + 255) / 256, 256>>>(conv_w, v);
    prep_cvb_kernel<<<1, 256>>>(conv_b, v, vb);
    prep_Wh_kernel<<<(KF_PAN * 4 * CH * 4 + 255) / 256, 256>>>(conv_w);
    round_emb_kernel<<<(VOCAB * WD / 4 + 255) / 256, 256>>>(emb);

    // 2. Q = embT @ M -> fp16 Q table  (tf32 mma.sync)
    {
        dim3 grid(NQ_PAD / 80, VOCAB / 128);
        tgemm_kernel<80><<<grid, 128, SMEM3(80)>>>(pembT, pMpi, pQh,
                                                   VOCAB, 600, WD, NQ_PAD);
    }

    // 3. attention scores (fp16 gathers, HW tanh)
    score_kernel<<<B_SZ / 8, 256>>>(tok, q);

    // 4. softmax stats (two-stage)
    {
        dim3 pgrid(NW, 8);
        softmax_part_kernel<<<pgrid, 512>>>();
        softmax_comb_kernel<<<1, 32>>>();
    }

    // 5. build G (fp16 plain layout) and sum-alpha
    gbuild_kernel<<<B_SZ, 96>>>(tok, emb);

    // 6. e = Gh @ Wh + salpha * conv_b  (fp16 HMMA)
    {
        dim3 grid(CH / 80, B_SZ / 128);
        hgemm_kernel<<<grid, 128, HSMEM>>>(pGh, pWh, out, psal, conv_b);
    }
}

// round 17
// speedup vs baseline: 1.2311x; 1.0921x over previous
#include <cuda_runtime.h>
#include <cuda_fp16.h>
#include <math.h>
#include <stdint.h>

#define B_SZ   32768
#define NW     30
#define VOCAB  32000
#define WD     300
#define CH     400
#define AD     200

#define KQ_PAN 19                  // ceil(300/16) panels (Q gemm)
#define KQ_PAD (KQ_PAN * 16)       // 304
#define KF_PAN 57                  // ceil(900/16) panels (final gemm)
#define KF_PAD (KF_PAN * 16)       // 912
#define NQ_PAD 640                 // Q-gemm B cols padded to 80-mult

// ---------------- scratch (static device globals; no allocation) ----------------
__device__ __align__(16) float  g_cvb[AD];
__device__ __align__(16) __half g_Qh[VOCAB * 600];               // fp16 Q table (38.4 MB)
__device__ __align__(16) float  g_aT[NW * B_SZ];
__device__ float g_mx[NW];
__device__ float g_isum[NW];
__device__ float g_pm[NW * 8];
__device__ float g_ps[NW * 8];
__device__ __align__(16) __half g_Gh[(size_t)B_SZ * KF_PAD];     // fp16 G, plain rows (59.8 MB)
__device__ float g_salpha[B_SZ];
__device__ __align__(16) __half g_Wh[KF_PAN * 4 * CH * 4];       // fp16 B-quad (final gemm)
__device__ __align__(16) __half g_Mh[KQ_PAN * 4 * NQ_PAD * 4];   // fp16 B-quad (Q gemm)
__device__ __align__(16) __half g_embH[VOCAB * KQ_PAD];          // fp16 emb, padded rows (19.5 MB)

// HW tanh: single MUFU op (sm_75+)
__device__ __forceinline__ float htanh(float x)
{
    float r;
    asm("tanh.approx.f32 %0, %1;" : "=f"(r) : "f"(x));
    return r;
}

// ---------------- prep kernels ----------------
// fp16 B-quad layout for the FINAL gemm (validated in R12/R16):
// g_Wh[((pnl*4 + j)*CH + n)*4 + q] = Wc2[k][n], k = pnl*16 + 2j + (q&1) + (q>>1)*8
__global__ void prep_Wh_kernel(const float* __restrict__ conv_w)
{
    int idx = blockIdx.x * blockDim.x + threadIdx.x;
    if (idx >= KF_PAN * 4 * CH * 4) return;
    const int q   = idx & 3;
    const int n   = (idx >> 2) % CH;
    const int j   = ((idx >> 2) / CH) & 3;
    const int pnl = idx / (4 * CH * 4);
    const int k   = pnl * 16 + 2 * j + (q & 1) + (q >> 1) * 8;
    float val = 0.f;
    if (k < 900) {
        const int sl = k / WD;
        const int i  = k % WD;
        val = conv_w[n * 900 + i * 3 + sl];
    }
    g_Wh[idx] = __float2half_rn(val);
}

// fp16 B-quad layout for the Q gemm: same index math, B = M[k=i][n=ks*200+a]
__global__ void prep_Mh_kernel(const float* __restrict__ conv_w, const float* __restrict__ v)
{
    int idx = blockIdx.x * blockDim.x + threadIdx.x;
    if (idx >= KQ_PAN * 4 * NQ_PAD * 4) return;
    const int q   = idx & 3;
    const int n   = (idx >> 2) % NQ_PAD;
    const int j   = ((idx >> 2) / NQ_PAD) & 3;
    const int pnl = idx / (4 * NQ_PAD * 4);
    const int k   = pnl * 16 + 2 * j + (q & 1) + (q >> 1) * 8;   // = word index i
    float val = 0.f;
    if (k < WD && n < 600) {
        const int ks = n / 200;
        const int a  = n % 200;
        float s = 0.f;
        #pragma unroll 4
        for (int o = 0; o < CH; o++)
            s += conv_w[o * (WD * 3) + k * 3 + ks] * v[o * AD + a];
        val = s;
    }
    g_Mh[idx] = __float2half_rn(val);
}

__global__ void prep_cvb_kernel(const float* __restrict__ conv_b,
                                const float* __restrict__ v,
                                const float* __restrict__ vb)
{
    int a = blockIdx.x * blockDim.x + threadIdx.x;
    if (a >= AD) return;
    float s = vb[a];
    for (int o = 0; o < CH; o++) s += conv_b[o] * v[o * AD + a];
    g_cvb[a] = s;
}

// fp16 emb copy with 304-half padded rows (pads stay zero: never written)
__global__ void round_embH_kernel(const float* __restrict__ emb)
{
    int idx = blockIdx.x * blockDim.x + threadIdx.x;     // float4 chunk id
    const int nch = VOCAB * (WD / 4);                    // 2,400,000
    if (idx >= nch) return;
    const int row = idx / (WD / 4);
    const int c   = idx % (WD / 4);
    const float4 v = *reinterpret_cast<const float4*>(emb + (size_t)row * WD + c * 4);
    uint2 h;
    *reinterpret_cast<__half2*>(&h.x) = __floats2half2_rn(v.x, v.y);
    *reinterpret_cast<__half2*>(&h.y) = __floats2half2_rn(v.z, v.w);
    *reinterpret_cast<uint2*>(g_embH + (size_t)row * KQ_PAD + c * 4) = h;
}

// ---------------- asm helpers ----------------
__device__ __forceinline__ void mma_f16(float* c,
                                        uint32_t a0, uint32_t a1, uint32_t a2, uint32_t a3,
                                        uint32_t b0, uint32_t b1)
{
    asm volatile(
        "mma.sync.aligned.m16n8k16.row.col.f32.f16.f16.f32 "
        "{%0,%1,%2,%3}, {%4,%5,%6,%7}, {%8,%9}, {%0,%1,%2,%3};\n"
        : "+f"(c[0]), "+f"(c[1]), "+f"(c[2]), "+f"(c[3])
        : "r"(a0), "r"(a1), "r"(a2), "r"(a3), "r"(b0), "r"(b1));
}
__device__ __forceinline__ void cp16(uint32_t dst, const void* src)
{
    asm volatile("cp.async.cg.shared.global [%0], [%1], 16;\n"
                 :: "r"(dst), "l"(src));
}

#define STAGES 4

// ---------------- unified fp16 HMMA GEMM ----------------
// C[?, N] = A[?, Kpad] @ Bq (+ rs[m]*bias[n] when !OUT_HALF).
// A: plain fp16 rows of Kpad halfs (Kpad mult of 16, pads zero).
// Bq: fp16 B-quad layout [nPan][4][BLD][4] (pads zero).
// Block tile 128 x 80, 128 threads (4 warps 2x2), warp tile 64x40.
#define HA_W 12       // 8 data words + 4 pad (conflict-free frag loads)
#define HB_W 168      // 160 data + 8 pad
#define HST_W (128 * HA_W + 4 * HB_W)    // words/stage
#define HSMEM (STAGES * HST_W * 4)       // 35328 bytes

template<int OUT_HALF>
__global__ __launch_bounds__(128, 3)
void hgemm_kernel(const __half* __restrict__ A, const __half* __restrict__ Bq,
                  void* __restrict__ Cv, int N, int Kpad, int nPan, int BLD,
                  const float* __restrict__ rs, const float* __restrict__ bias)
{
    extern __shared__ __align__(16) uint32_t smem[];
    const uint32_t s_base = (uint32_t)__cvta_generic_to_shared(smem);

    const int tid    = threadIdx.x;
    const int lane   = tid & 31;
    const int warp   = tid >> 5;
    const int warp_m = warp & 1;
    const int warp_n = warp >> 1;
    const int m0 = blockIdx.y * 128;
    const int n0 = blockIdx.x * 80;

    float acc[4][5][4];
    #pragma unroll
    for (int mt = 0; mt < 4; mt++)
        #pragma unroll
        for (int nt = 0; nt < 5; nt++)
            #pragma unroll
            for (int i = 0; i < 4; i++) acc[mt][nt][i] = 0.f;

    auto issue_panel = [&](int pnl) {
        const int s = pnl & (STAGES - 1);
        const uint32_t abase = s_base + (s * HST_W) * 4;
        const uint32_t bbase = abase + 128 * HA_W * 4;
        // A: 128 rows x 2 x 16B chunks
        #pragma unroll
        for (int r = 0; r < 2; r++) {
            const int idx = tid + r * 128;
            const int row = idx >> 1;
            const int ch  = idx & 1;
            const __half* src = A + (size_t)(m0 + row) * Kpad + pnl * 16 + ch * 8;
            cp16(abase + (row * HA_W + ch * 4) * 4, src);
        }
        // B: 4 j-rows x 40 x 16B chunks
        #pragma unroll
        for (int r = 0; r < 2; r++) {
            const int idx = tid + r * 128;
            if (idx < 160) {
                const int j  = idx / 40;
                const int ch = idx % 40;
                const __half* src = Bq + ((size_t)(pnl * 4 + j) * BLD + n0) * 4 + ch * 8;
                cp16(bbase + (j * HB_W + ch * 4) * 4, src);
            }
        }
        asm volatile("cp.async.commit_group;\n");
    };

    issue_panel(0);
    issue_panel(1);
    issue_panel(2);

    for (int it = 0; it < nPan; ++it) {
        asm volatile("cp.async.wait_group %0;\n" :: "n"(STAGES - 2));
        __syncthreads();

        const int s = it & (STAGES - 1);
        const uint32_t* Asb = smem + s * HST_W;
        const uint32_t* Bsb = Asb + 128 * HA_W;

        const int j = lane & 3;
        uint32_t af[4][4];
        uint32_t bf[5][2];
        #pragma unroll
        for (int mt = 0; mt < 4; mt++) {
            const int rb = warp_m * 64 + mt * 16 + (lane >> 2);
            af[mt][0] = Asb[rb * HA_W + j];
            af[mt][1] = Asb[(rb + 8) * HA_W + j];
            af[mt][2] = Asb[rb * HA_W + j + 4];
            af[mt][3] = Asb[(rb + 8) * HA_W + j + 4];
        }
        #pragma unroll
        for (int nt = 0; nt < 5; nt++) {
            const int nc = warp_n * 40 + nt * 8 + (lane >> 2);
            uint2 bv = *reinterpret_cast<const uint2*>(&Bsb[j * HB_W + nc * 2]);
            bf[nt][0] = bv.x;
            bf[nt][1] = bv.y;
        }
        #pragma unroll
        for (int mt = 0; mt < 4; mt++)
            #pragma unroll
            for (int nt = 0; nt < 5; nt++)
                mma_f16(acc[mt][nt], af[mt][0], af[mt][1], af[mt][2], af[mt][3],
                        bf[nt][0], bf[nt][1]);

        if (it + STAGES - 1 < nPan) {
            issue_panel(it + STAGES - 1);
        } else {
            asm volatile("cp.async.commit_group;\n");
        }
    }

    // ---- epilogue ----
    #pragma unroll
    for (int mt = 0; mt < 4; mt++) {
        const int row0 = m0 + warp_m * 64 + mt * 16 + (lane >> 2);
        const int row1 = row0 + 8;
        float r0 = 0.f, r1 = 0.f;
        if (!OUT_HALF) { r0 = rs[row0]; r1 = rs[row1]; }
        #pragma unroll
        for (int nt = 0; nt < 5; nt++) {
            const int col = n0 + warp_n * 40 + nt * 8 + (lane & 3) * 2;
            if (col < N) {
                if (OUT_HALF) {
                    __half* C = (__half*)Cv;
                    *reinterpret_cast<__half2*>(C + (size_t)row0 * N + col) =
                        __floats2half2_rn(acc[mt][nt][0], acc[mt][nt][1]);
                    *reinterpret_cast<__half2*>(C + (size_t)row1 * N + col) =
                        __floats2half2_rn(acc[mt][nt][2], acc[mt][nt][3]);
                } else {
                    float* C = (float*)Cv;
                    const float b0 = bias[col], b1 = bias[col + 1];
                    *reinterpret_cast<float2*>(C + (size_t)row0 * N + col) =
                        make_float2(acc[mt][nt][0] + r0 * b0, acc[mt][nt][1] + r0 * b1);
                    *reinterpret_cast<float2*>(C + (size_t)row1 * N + col) =
                        make_float2(acc[mt][nt][2] + r1 * b0, acc[mt][nt][3] + r1 * b1);
                }
            }
        }
    }
}

// ---------------- scores: fp16 Q gathers + HW tanh ----------------
__global__ __launch_bounds__(256)
void score_kernel(const int* __restrict__ tok, const float* __restrict__ qv)
{
    __shared__ float4 sq[AD / 4];
    __shared__ float4 scvb[AD / 4];
    __shared__ int stok[8][NW];

    const int tid = threadIdx.x;
    const int wid = tid >> 5;
    const int lane = tid & 31;
    const int b = blockIdx.x * 8 + wid;

    if (tid < AD / 4) {
        sq[tid]   = reinterpret_cast<const float4*>(qv)[tid];
        scvb[tid] = reinterpret_cast<const float4*>(g_cvb)[tid];
    }
    if (lane < NW) stok[wid][lane] = tok[b * NW + lane];
    __syncthreads();

    for (int n = 0; n < NW; n++) {
        const int tc  = stok[wid][n];
        const int tp  = (n > 0)      ? stok[wid][n - 1] : -1;
        const int tn2 = (n < NW - 1) ? stok[wid][n + 1] : -1;
        const uint2* q1 = reinterpret_cast<const uint2*>(g_Qh + (size_t)tc * 600 + 200);
        const uint2* q0 = (tp  >= 0) ? reinterpret_cast<const uint2*>(g_Qh + (size_t)tp  * 600)       : nullptr;
        const uint2* q2 = (tn2 >= 0) ? reinterpret_cast<const uint2*>(g_Qh + (size_t)tn2 * 600 + 400) : nullptr;

        float s = 0.f;
        #pragma unroll
        for (int a4 = lane; a4 < AD / 4; a4 += 32) {
            float4 h = scvb[a4];
            {
                uint2 u = q1[a4];
                float2 lo = __half22float2(*reinterpret_cast<__half2*>(&u.x));
                float2 hi = __half22float2(*reinterpret_cast<__half2*>(&u.y));
                h.x += lo.x; h.y += lo.y; h.z += hi.x; h.w += hi.y;
            }
            if (q0) {
                uint2 u = q0[a4];
                float2 lo = __half22float2(*reinterpret_cast<__half2*>(&u.x));
                float2 hi = __half22float2(*reinterpret_cast<__half2*>(&u.y));
                h.x += lo.x; h.y += lo.y; h.z += hi.x; h.w += hi.y;
            }
            if (q2) {
                uint2 u = q2[a4];
                float2 lo = __half22float2(*reinterpret_cast<__half2*>(&u.x));
                float2 hi = __half22float2(*reinterpret_cast<__half2*>(&u.y));
                h.x += lo.x; h.y += lo.y; h.z += hi.x; h.w += hi.y;
            }
            float4 qq = sq[a4];
            s += htanh(h.x) * qq.x + htanh(h.y) * qq.y + htanh(h.z) * qq.z + htanh(h.w) * qq.w;
        }
        #pragma unroll
        for (int off = 16; off; off >>= 1)
            s += __shfl_down_sync(0xffffffffu, s, off);
        if (lane == 0) g_aT[n * B_SZ + b] = s;
    }
}

// ---------------- two-stage softmax stats ----------------
__global__ __launch_bounds__(512)
void softmax_part_kernel()
{
    __shared__ float red[512];
    const int n = blockIdx.x;
    const int c = blockIdx.y;
    const int tid = threadIdx.x;
    const float* row = g_aT + (size_t)n * B_SZ + c * 4096;

    float mx = -INFINITY;
    #pragma unroll
    for (int i = 0; i < 8; i++) mx = fmaxf(mx, row[tid + i * 512]);
    red[tid] = mx;
    __syncthreads();
    for (int s = 256; s > 0; s >>= 1) {
        if (tid < s) red[tid] = fmaxf(red[tid], red[tid + s]);
        __syncthreads();
    }
    mx = red[0];
    __syncthreads();

    float sum = 0.f;
    #pragma unroll
    for (int i = 0; i < 8; i++) sum += __expf(row[tid + i * 512] - mx);
    red[tid] = sum;
    __syncthreads();
    for (int s = 256; s > 0; s >>= 1) {
        if (tid < s) red[tid] += red[tid + s];
        __syncthreads();
    }
    if (tid == 0) { g_pm[n * 8 + c] = mx; g_ps[n * 8 + c] = red[0]; }
}

__global__ void softmax_comb_kernel()
{
    const int n = threadIdx.x;
    if (n >= NW) return;
    float M = -INFINITY;
    #pragma unroll
    for (int c = 0; c < 8; c++) M = fmaxf(M, g_pm[n * 8 + c]);
    float S = 0.f;
    #pragma unroll
    for (int c = 0; c < 8; c++) S += g_ps[n * 8 + c] * __expf(g_pm[n * 8 + c] - M);
    g_mx[n] = M;
    g_isum[n] = 1.f / S;
}

// ---------------- build G (fp32 emb gathers, fp16 coalesced plain stores) -------
__global__ __launch_bounds__(96)
void gbuild_kernel(const int* __restrict__ tok, const float* __restrict__ emb)
{
    __shared__ float sal[NW + 2];
    __shared__ int stok[NW];
    const int b = blockIdx.x;
    const int tid = threadIdx.x;

    if (tid < NW) {
        sal[tid + 1] = __expf(g_aT[tid * B_SZ + b] - g_mx[tid]) * g_isum[tid];
        stok[tid] = tok[b * NW + tid];
    }
    if (tid == NW)     sal[0] = 0.f;
    if (tid == NW + 1) sal[NW + 1] = 0.f;
    __syncthreads();

    if (tid == 0) {
        float s = 0.f;
        #pragma unroll
        for (int n = 1; n <= NW; n++) s += sal[n];
        g_salpha[b] = s;
    }

    if (tid < WD / 4) {
        float4 g0 = make_float4(0.f, 0.f, 0.f, 0.f);
        float4 g1 = g0, g2 = g0;
        #pragma unroll
        for (int m = 0; m < NW; m++) {
            const float4 e = reinterpret_cast<const float4*>(
                emb + (size_t)stok[m] * WD)[tid];
            const float w1 = sal[m + 1];
            const float w0 = sal[m + 2];
            const float w2 = sal[m];
            g1.x += w1 * e.x; g1.y += w1 * e.y; g1.z += w1 * e.z; g1.w += w1 * e.w;
            g0.x += w0 * e.x; g0.y += w0 * e.y; g0.z += w0 * e.z; g0.w += w0 * e.w;
            g2.x += w2 * e.x; g2.y += w2 * e.y; g2.z += w2 * e.z; g2.w += w2 * e.w;
        }
        __half* gp = g_Gh + (size_t)b * KF_PAD;
        uint2 u0, u1, u2;
        *reinterpret_cast<__half2*>(&u0.x) = __floats2half2_rn(g0.x, g0.y);
        *reinterpret_cast<__half2*>(&u0.y) = __floats2half2_rn(g0.z, g0.w);
        *reinterpret_cast<__half2*>(&u1.x) = __floats2half2_rn(g1.x, g1.y);
        *reinterpret_cast<__half2*>(&u1.y) = __floats2half2_rn(g1.z, g1.w);
        *reinterpret_cast<__half2*>(&u2.x) = __floats2half2_rn(g2.x, g2.y);
        *reinterpret_cast<__half2*>(&u2.y) = __floats2half2_rn(g2.z, g2.w);
        *reinterpret_cast<uint2*>(gp +       tid * 4) = u0;
        *reinterpret_cast<uint2*>(gp + 300 + tid * 4) = u1;
        *reinterpret_cast<uint2*>(gp + 600 + tid * 4) = u2;
    }
}

// ---------------- launch ----------------
extern "C" void kernel_launch(void* const* d_in, const int* in_sizes, int n_in,
                              void* d_out, int out_size)
{
    const int*   tok    = (const int*)  d_in[0];
    const float* emb    = (const float*)d_in[1];
    const float* conv_w = (const float*)d_in[2];
    const float* conv_b = (const float*)d_in[3];
    const float* v      = (const float*)d_in[4];
    const float* vb     = (const float*)d_in[5];
    const float* q      = (const float*)d_in[6];
    float* out = (float*)d_out;

    float* psal;
    __half *pQh, *pGh, *pWh, *pMh, *pembH;
    cudaGetSymbolAddress((void**)&pQh,   g_Qh);
    cudaGetSymbolAddress((void**)&pGh,   g_Gh);
    cudaGetSymbolAddress((void**)&pWh,   g_Wh);
    cudaGetSymbolAddress((void**)&pMh,   g_Mh);
    cudaGetSymbolAddress((void**)&pembH, g_embH);
    cudaGetSymbolAddress((void**)&psal,  g_salpha);

    cudaFuncSetAttribute((const void*)hgemm_kernel<0>,
                         cudaFuncAttributeMaxDynamicSharedMemorySize, HSMEM);
    cudaFuncSetAttribute((const void*)hgemm_kernel<1>,
                         cudaFuncAttributeMaxDynamicSharedMemorySize, HSMEM);

    // 1. prep (fp16 B-quad operands, cvb, fp16 padded emb copy)
    prep_Mh_kernel<<<(KQ_PAN * 4 * NQ_PAD * 4 + 255) / 256, 256>>>(conv_w, v);
    prep_cvb_kernel<<<1, 256>>>(conv_b, v, vb);
    prep_Wh_kernel<<<(KF_PAN * 4 * CH * 4 + 255) / 256, 256>>>(conv_w);
    round_embH_kernel<<<(VOCAB * (WD / 4) + 255) / 256, 256>>>(emb);

    // 2. Q = embH @ Mh -> fp16 Q table  (fp16 HMMA)
    {
        dim3 grid(NQ_PAD / 80, VOCAB / 128);
        hgemm_kernel<1><<<grid, 128, HSMEM>>>(pembH, pMh, (void*)pQh,
                                              600, KQ_PAD, KQ_PAN, NQ_PAD,
                                              nullptr, nullptr);
    }

    // 3. attention scores (fp16 gathers, HW tanh)
    score_kernel<<<B_SZ / 8, 256>>>(tok, q);

    // 4. softmax stats (two-stage)
    {
        dim3 pgrid(NW, 8);
        softmax_part_kernel<<<pgrid, 512>>>();
        softmax_comb_kernel<<<1, 32>>>();
    }

    // 5. build G (fp16 plain layout) and sum-alpha
    gbuild_kernel<<<B_SZ, 96>>>(tok, emb);

    // 6. e = Gh @ Wh + salpha * conv_b  (fp16 HMMA)
    {
        dim3 grid(CH / 80, B_SZ / 128);
        hgemm_kernel<0><<<grid, 128, HSMEM>>>(pGh, pWh, (void*)out,
                                              CH, KF_PAD, KF_PAN, CH,
                                              psal, conv_b);
    }
}